// round 8
// baseline (speedup 1.0000x reference)
#include <cuda_runtime.h>
#include <cstdint>

// LocalAtten: NB=4, NLOC=2048, NNEI=64, NI=ND=64, NH=4
//   P[h] = Wq_h @ Wkv_k_h^T / 8   -> s[j,h] = g1 . P_h . gg1_j
//   M[h] = Wkv_v_h @ Wh_h         -> out = sum_h u_h @ M_h + bh
// R8: 3-kernel split (projW GEMV -> attention -> projOut GEMV), register-
// cached P/M columns, all-256-thread attention phases, fma.rn.f32x2 packing.
// Fixes vs R7: u64 carrier for f32x2 asm ("l" constraint needs int64), and
// corrected aw indexing in the u-phase (one 16B element per j).

__device__ float d_P[4 * 64 * 64];          // [h][ip][i]
__device__ float d_M[4 * 64 * 64];          // [h][i][o]
__device__ float d_W[8192 * 256];           // [bl][h*64+i]
__device__ float d_U[8192 * 256];           // [bl][h*64+i]

typedef unsigned long long u64;

// ---- f32x2 helpers (carrier = u64 holding 2 packed floats) -----------------
__device__ __forceinline__ void ffma2(u64& d, u64 a, u64 b) {
    asm("fma.rn.f32x2 %0, %1, %2, %0;" : "+l"(d) : "l"(a), "l"(b));
}
__device__ __forceinline__ u64 pack2(float x, float y) {
    u64 d;
    asm("mov.b64 %0, {%1, %2};" : "=l"(d) : "f"(x), "f"(y));
    return d;
}
__device__ __forceinline__ float2 unpack2(u64 d) {
    float2 f;
    asm("mov.b64 {%0, %1}, %2;" : "=f"(f.x), "=f"(f.y) : "l"(d));
    return f;
}
__device__ __forceinline__ float hsum2(u64 d) {
    float2 f = unpack2(d);
    return f.x + f.y;
}
// swizzle helper: within a warp (consecutive rows) same l maps to distinct banks.
__device__ __forceinline__ int lane_xor(int row) { return row & 31; }

// ---------------------------------------------------------------------------
// Precompute P and M. grid (4 heads, 2 matrices), 256 threads.
// ---------------------------------------------------------------------------
__global__ __launch_bounds__(256) void la_precompute(
    const float* __restrict__ Wq,   // (64, 256)  col = d*4 + h
    const float* __restrict__ Wkv,  // (64, 512)  col = d*8 + c
    const float* __restrict__ Wh)   // (256, 64)  row = h*64 + d
{
    int h = blockIdx.x;
    int mat = blockIdx.y;
    int t = threadIdx.x;
    __shared__ float A[64][65];
    __shared__ float B[64][65];

    if (mat == 0) {
        for (int e = t; e < 4096; e += 256) {
            int r = e >> 6, d = e & 63;
            A[r][d] = Wq[r * 256 + d * 4 + h];
            B[r][d] = Wkv[r * 512 + d * 8 + h];
        }
        __syncthreads();
        for (int e = t; e < 4096; e += 256) {
            int ip = e >> 6, i = e & 63;
            float acc = 0.f;
#pragma unroll 8
            for (int d = 0; d < 64; d++) acc += A[ip][d] * B[i][d];
            d_P[(h * 64 + ip) * 64 + i] = acc * 0.125f;
        }
    } else {
        for (int e = t; e < 4096; e += 256) {
            int r = e >> 6, c = e & 63;
            A[r][c] = Wkv[r * 512 + c * 8 + 4 + h];
            B[r][c] = Wh[(h * 64 + r) * 64 + c];
        }
        __syncthreads();
        for (int e = t; e < 4096; e += 256) {
            int i = e >> 6, o = e & 63;
            float acc = 0.f;
#pragma unroll 8
            for (int d = 0; d < 64; d++) acc += A[i][d] * B[d][o];
            d_M[(h * 64 + i) * 64 + o] = acc;
        }
    }
}

// ---------------------------------------------------------------------------
// k1: W projection. d_W[bl][h*64+i] = sum_ip g1[bl][ip] * P[h][ip][i]
// grid 256 CTAs x 32 locs, 256 threads (h = t>>6, i = t&63).
// ---------------------------------------------------------------------------
__global__ __launch_bounds__(256) void la_projW(const float* __restrict__ g1)
{
    __shared__ __align__(16) float g1s[32 * 64];
    int t = threadIdx.x;
    int h = t >> 6, i = t & 63;
    int base = blockIdx.x * 32;

    for (int e = t; e < 512; e += 256)
        ((float4*)g1s)[e] = ((const float4*)(g1 + (size_t)base * 64))[e];

    // register-cache P column, packed over ip pairs
    u64 Pr[32];
    const float* Pp = d_P + h * 4096 + i;
#pragma unroll
    for (int k = 0; k < 32; k++)
        Pr[k] = pack2(Pp[(2 * k) * 64], Pp[(2 * k + 1) * 64]);
    __syncthreads();

    for (int l = 0; l < 32; l++) {
        const ulonglong2* gd = (const ulonglong2*)(g1s + l * 64);
        u64 acc_a = pack2(0.f, 0.f), acc_b = pack2(0.f, 0.f);
#pragma unroll
        for (int q = 0; q < 16; q++) {
            ulonglong2 gv = gd[q];  // .x = floats(4q,4q+1), .y = (4q+2,4q+3)
            ffma2(acc_a, gv.x, Pr[2 * q]);
            ffma2(acc_b, gv.y, Pr[2 * q + 1]);
        }
        d_W[(size_t)(base + l) * 256 + t] = hsum2(acc_a) + hsum2(acc_b);
    }
}

// ---------------------------------------------------------------------------
// k2: attention. One CTA per loc, 8192 CTAs x 256 threads.
// ---------------------------------------------------------------------------
__global__ __launch_bounds__(256) void la_attn(
    const float* __restrict__ gg1,  // (8192, 64, 64)
    const int* __restrict__ msk)    // (8192, 64) int32 bool
{
    __shared__ __align__(16) float4 ggS[64 * 16];    // swizzled tile, 16KB
    __shared__ __align__(16) float  Wl[256];         // [h*64+i]
    __shared__ __align__(16) float  aw[256];         // [j*4+h]
    __shared__ __align__(16) float  partT[16][68];   // [(q*4+h)][j or i]
    __shared__ int idxs[64];
    __shared__ int mcnt;

    int bl = blockIdx.x;
    int t = threadIdx.x;
    int lane = t & 31;

    Wl[t] = d_W[(size_t)bl * 256 + t];

    if (t < 32) {  // ordered mask compaction, warp 0
        const int* mp = msk + (size_t)bl * 64;
        int base = 0;
#pragma unroll
        for (int c = 0; c < 2; c++) {
            int j = c * 32 + lane;
            bool bit = mp[j] != 0;
            unsigned bal = __ballot_sync(0xffffffffu, bit);
            int pos = base + __popc(bal & ((1u << lane) - 1u));
            if (bit) idxs[pos] = j;
            base += __popc(bal);
        }
        if (lane == 0) mcnt = base;
    }
    __syncthreads();
    int m = mcnt;

    // gather unmasked rows, swizzled slot = qq ^ (jj&15)
    const float* ggb = gg1 + (size_t)bl * 4096;
    for (int e = t; e < m * 16; e += 256) {
        int jj = e >> 4, qq = e & 15;
        float4 v = *(const float4*)(ggb + idxs[jj] * 64 + qq * 4);
        ggS[jj * 16 + (qq ^ (jj & 15))] = v;
    }
    __syncthreads();

    // logits: thread (q, j) handles i in [q*16, q*16+16), all 4 heads.
    {
        int q = t >> 6, j = t & 63, jx = j & 15;
        u64 a0 = pack2(0.f, 0.f), a1 = a0, a2 = a0, a3 = a0;
        const ulonglong2* wd = (const ulonglong2*)Wl;  // wd[h*16+qq] = i 4qq..4qq+3
        const ulonglong2* gd = (const ulonglong2*)ggS;
#pragma unroll
        for (int k = 0; k < 4; k++) {
            int qq = q * 4 + k;
            ulonglong2 gv = gd[j * 16 + (qq ^ jx)];
            ulonglong2 w0 = wd[qq];
            ulonglong2 w1 = wd[16 + qq];
            ulonglong2 w2 = wd[32 + qq];
            ulonglong2 w3 = wd[48 + qq];
            ffma2(a0, gv.x, w0.x); ffma2(a0, gv.y, w0.y);
            ffma2(a1, gv.x, w1.x); ffma2(a1, gv.y, w1.y);
            ffma2(a2, gv.x, w2.x); ffma2(a2, gv.y, w2.y);
            ffma2(a3, gv.x, w3.x); ffma2(a3, gv.y, w3.y);
        }
        partT[q * 4 + 0][j] = hsum2(a0);
        partT[q * 4 + 1][j] = hsum2(a1);
        partT[q * 4 + 2][j] = hsum2(a2);
        partT[q * 4 + 3][j] = hsum2(a3);
    }
    __syncthreads();

    // softmax: warp per head over compacted j (combine 4 quarters inline)
    if (t < 128) {
        int h = t >> 5, ln = t & 31;
        float x0 = -1e30f, x1 = -1e30f;
        if (ln < m)
            x0 = partT[h][ln] + partT[4 + h][ln] + partT[8 + h][ln] + partT[12 + h][ln];
        if (ln + 32 < m)
            x1 = partT[h][ln + 32] + partT[4 + h][ln + 32] + partT[8 + h][ln + 32] + partT[12 + h][ln + 32];
        float mx = fmaxf(x0, x1);
#pragma unroll
        for (int off = 16; off; off >>= 1)
            mx = fmaxf(mx, __shfl_xor_sync(0xffffffffu, mx, off));
        float e0 = (ln < m) ? __expf(x0 - mx) : 0.f;
        float e1 = (ln + 32 < m) ? __expf(x1 - mx) : 0.f;
        float s = e0 + e1;
#pragma unroll
        for (int off = 16; off; off >>= 1)
            s += __shfl_xor_sync(0xffffffffu, s, off);
        float inv = (s > 0.f) ? 1.f / s : 0.f;
        aw[ln * 4 + h] = e0 * inv;
        aw[(ln + 32) * 4 + h] = e1 * inv;
    }
    __syncthreads();

    // u: thread (q, i) handles quarter of j-range, all 4 heads.
    {
        int q = t >> 6, i = t & 63;
        int ihi = i >> 2, ilo = i & 3;
        int j0 = (m * q) >> 2, j1 = (m * (q + 1)) >> 2;
        u64 u01 = pack2(0.f, 0.f), u23 = u01;
        const ulonglong2* ad = (const ulonglong2*)aw;  // ad[j] = {heads(0,1), heads(2,3)}
        const float* ggf = (const float*)ggS;
        for (int j = j0; j < j1; j++) {
            ulonglong2 a = ad[j];
            float v = ggf[j * 64 + ((ihi ^ (j & 15)) << 2) + ilo];
            u64 vb = pack2(v, v);
            ffma2(u01, vb, a.x);
            ffma2(u23, vb, a.y);
        }
        float2 f01 = unpack2(u01), f23 = unpack2(u23);
        partT[q * 4 + 0][i] = f01.x;
        partT[q * 4 + 1][i] = f01.y;
        partT[q * 4 + 2][i] = f23.x;
        partT[q * 4 + 3][i] = f23.y;
    }
    __syncthreads();

    {   // write U: t = h*64+i
        int h = t >> 6, i = t & 63;
        float val = partT[h][i] + partT[4 + h][i] + partT[8 + h][i] + partT[12 + h][i];
        d_U[(size_t)bl * 256 + t] = val;
    }
}

// ---------------------------------------------------------------------------
// k3: out projection. out[l][o] = bh[o] + sum_h sum_i U[l][h*64+i]*M[h][i][o]
// grid 256 CTAs x 32 locs, 256 threads (h = t>>6, o = t&63).
// ---------------------------------------------------------------------------
__global__ __launch_bounds__(256) void la_projOut(
    const float* __restrict__ bh, float* __restrict__ out)
{
    __shared__ __align__(16) float us[32 * 256];  // 32KB, reused as partials
    int t = threadIdx.x;
    int h = t >> 6, o = t & 63;
    int base = blockIdx.x * 32;

    for (int e = t; e < 2048; e += 256)
        ((float4*)us)[e] = ((const float4*)(d_U + (size_t)base * 256))[e];

    // register-cache M column, packed over i pairs
    u64 Mr[32];
    const float* Mp = d_M + h * 4096 + o;
#pragma unroll
    for (int k = 0; k < 32; k++)
        Mr[k] = pack2(Mp[(2 * k) * 64], Mp[(2 * k + 1) * 64]);
    __syncthreads();

    float pl[32];
#pragma unroll 4
    for (int l = 0; l < 32; l++) {
        const ulonglong2* ud = (const ulonglong2*)(us + l * 256 + h * 64);
        u64 acc_a = pack2(0.f, 0.f), acc_b = acc_a;
#pragma unroll
        for (int q = 0; q < 16; q++) {
            ulonglong2 uv = ud[q];
            ffma2(acc_a, uv.x, Mr[2 * q]);
            ffma2(acc_b, uv.y, Mr[2 * q + 1]);
        }
        pl[l] = hsum2(acc_a) + hsum2(acc_b);
    }
    __syncthreads();  // done reading us; reuse for partials

    // partial store: row = t (= h*64+o), swizzled slot over l -> conflict-free
    {
#pragma unroll
        for (int l = 0; l < 32; l++)
            us[t * 32 + (l ^ lane_xor(t))] = pl[l];
    }
    __syncthreads();

    // final: 8 outputs per thread; sum the 4 head partials
#pragma unroll
    for (int r = 0; r < 8; r++) {
        int e = t + 256 * r;            // e = l*64 + o
        int l = e >> 6, oo = e & 63;
        float v = bh[oo];
#pragma unroll
        for (int hh = 0; hh < 4; hh++) {
            int row = hh * 64 + oo;
            v += us[row * 32 + (l ^ lane_xor(row))];
        }
        out[(size_t)(base + l) * 64 + oo] = v;
    }
}

// ---------------------------------------------------------------------------
extern "C" void kernel_launch(void* const* d_in, const int* in_sizes, int n_in,
                              void* d_out, int out_size)
{
    const float* g1 = (const float*)d_in[0];
    const float* gg1 = (const float*)d_in[1];
    const int* msk = (const int*)d_in[2];
    const float* Wq = (const float*)d_in[3];
    const float* Wkv = (const float*)d_in[4];
    const float* Wh = (const float*)d_in[5];
    const float* bh = (const float*)d_in[6];
    float* out = (float*)d_out;

    la_precompute<<<dim3(4, 2), 256>>>(Wq, Wkv, Wh);
    la_projW<<<256, 256>>>(g1);
    la_attn<<<8192, 256>>>(gg1, msk);
    la_projOut<<<256, 256>>>(bh, out);
}

// round 9
// speedup vs baseline: 1.1420x; 1.1420x over previous
#include <cuda_runtime.h>
#include <cstdint>

// LocalAtten: NB=4, NLOC=2048, NNEI=64, NI=ND=64, NH=4
//   P[h] = Wq_h @ Wkv_k_h^T / 8   -> s[j,h] = g1 . P_h . gg1_j
//   M[h] = Wkv_v_h @ Wh_h         -> out = sum_h u_h @ M_h + bh
// R9: merge of R5 (fused T=4, batched W/out phases, P/M L2-hot) and R8
// (all-256-thread logits/u phases, fma.rn.f32x2). No d_W/d_U round trip,
// no low-occupancy GEMV kernels.

__device__ float d_P[4 * 64 * 64];  // [h][ip][i]
__device__ float d_M[4 * 64 * 64];  // [h][i][o]

typedef unsigned long long u64;

// ---- f32x2 helpers (carrier = u64 holding 2 packed floats) -----------------
__device__ __forceinline__ void ffma2(u64& d, u64 a, u64 b) {
    asm("fma.rn.f32x2 %0, %1, %2, %0;" : "+l"(d) : "l"(a), "l"(b));
}
__device__ __forceinline__ u64 pack2(float x, float y) {
    u64 d;
    asm("mov.b64 %0, {%1, %2};" : "=l"(d) : "f"(x), "f"(y));
    return d;
}
__device__ __forceinline__ float2 unpack2(u64 d) {
    float2 f;
    asm("mov.b64 {%0, %1}, %2;" : "=f"(f.x), "=f"(f.y) : "l"(d));
    return f;
}
__device__ __forceinline__ float hsum2(u64 d) {
    float2 f = unpack2(d);
    return f.x + f.y;
}

// ---------------------------------------------------------------------------
// Precompute P and M. grid (4 heads, 2 matrices), 256 threads.
// ---------------------------------------------------------------------------
__global__ __launch_bounds__(256) void la_precompute(
    const float* __restrict__ Wq,   // (64, 256)  col = d*4 + h
    const float* __restrict__ Wkv,  // (64, 512)  col = d*8 + c
    const float* __restrict__ Wh)   // (256, 64)  row = h*64 + d
{
    int h = blockIdx.x;
    int mat = blockIdx.y;
    int t = threadIdx.x;
    __shared__ float A[64][65];
    __shared__ float B[64][65];

    if (mat == 0) {
        for (int e = t; e < 4096; e += 256) {
            int r = e >> 6, d = e & 63;
            A[r][d] = Wq[r * 256 + d * 4 + h];
            B[r][d] = Wkv[r * 512 + d * 8 + h];
        }
        __syncthreads();
        for (int e = t; e < 4096; e += 256) {
            int ip = e >> 6, i = e & 63;
            float acc = 0.f;
#pragma unroll 8
            for (int d = 0; d < 64; d++) acc += A[ip][d] * B[i][d];
            d_P[(h * 64 + ip) * 64 + i] = acc * 0.125f;
        }
    } else {
        for (int e = t; e < 4096; e += 256) {
            int r = e >> 6, c = e & 63;
            A[r][c] = Wkv[r * 512 + c * 8 + 4 + h];
            B[r][c] = Wh[(h * 64 + r) * 64 + c];
        }
        __syncthreads();
        for (int e = t; e < 4096; e += 256) {
            int i = e >> 6, o = e & 63;
            float acc = 0.f;
#pragma unroll 8
            for (int d = 0; d < 64; d++) acc += A[i][d] * B[d][o];
            d_M[(h * 64 + i) * 64 + o] = acc;
        }
    }
}

// ---------------------------------------------------------------------------
// Fused main kernel: one CTA per 4 locs. 2048 CTAs x 256 threads.
// ---------------------------------------------------------------------------
__global__ __launch_bounds__(256) void la_fused(
    const float* __restrict__ g1,   // (8192, 64)
    const float* __restrict__ gg1,  // (8192, 64, 64)
    const int* __restrict__ msk,    // (8192, 64) int32 bool
    const float* __restrict__ bh,   // (64,)
    float* __restrict__ out)        // (8192, 64)
{
    __shared__ __align__(16) float ggS[64 * 64];     // swizzled tile, 16KB
    __shared__ __align__(16) float Wl[4][256];       // [l][h*64+i]
    __shared__ __align__(16) float g1T[64 * 4];      // [ip*4 + l]
    __shared__ __align__(16) float uT[256 * 4];      // [(h*64+i)*4 + l]
    __shared__ __align__(16) float aw[256];          // [j*4 + h]
    __shared__ __align__(16) float partT[16][68];    // [(q*4+h)][j or i]
    __shared__ __align__(16) float pout[4][64 * 4];  // [h][o*4 + l]
    __shared__ int idxs[4][64];
    __shared__ int mcnt[4];

    int g = blockIdx.x;
    int t = threadIdx.x;
    int lane = t & 31, wid = t >> 5;

    // --- mask compaction: one warp per loc ---
    if (wid < 4) {
        const int* mp = msk + (size_t)(g * 4 + wid) * 64;
        int base = 0;
#pragma unroll
        for (int c = 0; c < 2; c++) {
            int j = c * 32 + lane;
            bool bit = mp[j] != 0;
            unsigned bal = __ballot_sync(0xffffffffu, bit);
            int pos = base + __popc(bal & ((1u << lane) - 1u));
            if (bit) idxs[wid][pos] = j;
            base += __popc(bal);
        }
        if (lane == 0) mcnt[wid] = base;
    }
    // --- g1 transposed staging: g1T[ip*4+l] = g1[loc l][ip] ---
    {
        int l = t >> 6, ip = t & 63;
        g1T[ip * 4 + l] = g1[(size_t)(g * 4 + l) * 64 + ip];
    }
    __syncthreads();

    // --- W phase, batched over 4 locs, f32x2 ---
    {   // thread (h = t>>6, i = t&63)
        int h = t >> 6, i = t & 63;
        const float* Pp = d_P + h * 4096 + i;
        const ulonglong2* gd = (const ulonglong2*)g1T;  // gd[ip] = {l01, l23}
        u64 a01 = pack2(0.f, 0.f), a23 = a01;
#pragma unroll 8
        for (int ip = 0; ip < 64; ip++) {
            float p = Pp[ip * 64];
            u64 pb = pack2(p, p);
            ulonglong2 gv = gd[ip];
            ffma2(a01, gv.x, pb);
            ffma2(a23, gv.y, pb);
        }
        float2 f01 = unpack2(a01), f23 = unpack2(a23);
        Wl[0][t] = f01.x;
        Wl[1][t] = f01.y;
        Wl[2][t] = f23.x;
        Wl[3][t] = f23.y;
    }

    // --- per-loc attention ---
    for (int l = 0; l < 4; l++) {
        int m = mcnt[l];

        // gather unmasked rows into swizzled tile (float4 slot = qq ^ (jj&15))
        const float* ggb = gg1 + (size_t)(g * 4 + l) * 4096;
        float4* ggS4 = (float4*)ggS;
        for (int e = t; e < m * 16; e += 256) {
            int jj = e >> 4, qq = e & 15;
            float4 v = *(const float4*)(ggb + idxs[l][jj] * 64 + qq * 4);
            ggS4[jj * 16 + (qq ^ (jj & 15))] = v;
        }
        __syncthreads();  // also orders Wl writes (first iter)

        // logits: thread (q = t>>6, j = t&63) handles i in [16q,16q+16), 4 heads
        {
            int q = t >> 6, j = t & 63, jx = j & 15;
            u64 a0 = pack2(0.f, 0.f), a1 = a0, a2 = a0, a3 = a0;
            const ulonglong2* wd = (const ulonglong2*)Wl[l];
            const ulonglong2* gd = (const ulonglong2*)ggS;
#pragma unroll
            for (int k = 0; k < 4; k++) {
                int qq = q * 4 + k;
                ulonglong2 gv = gd[j * 16 + (qq ^ jx)];
                ulonglong2 w0 = wd[qq];
                ulonglong2 w1 = wd[16 + qq];
                ulonglong2 w2 = wd[32 + qq];
                ulonglong2 w3 = wd[48 + qq];
                ffma2(a0, gv.x, w0.x); ffma2(a0, gv.y, w0.y);
                ffma2(a1, gv.x, w1.x); ffma2(a1, gv.y, w1.y);
                ffma2(a2, gv.x, w2.x); ffma2(a2, gv.y, w2.y);
                ffma2(a3, gv.x, w3.x); ffma2(a3, gv.y, w3.y);
            }
            partT[q * 4 + 0][j] = hsum2(a0);
            partT[q * 4 + 1][j] = hsum2(a1);
            partT[q * 4 + 2][j] = hsum2(a2);
            partT[q * 4 + 3][j] = hsum2(a3);
        }
        __syncthreads();

        // softmax: warp per head over compacted j (combine quarters inline)
        if (t < 128) {
            int h = t >> 5, ln = t & 31;
            float x0 = -1e30f, x1 = -1e30f;
            if (ln < m)
                x0 = partT[h][ln] + partT[4 + h][ln] + partT[8 + h][ln] + partT[12 + h][ln];
            if (ln + 32 < m)
                x1 = partT[h][ln + 32] + partT[4 + h][ln + 32] + partT[8 + h][ln + 32] + partT[12 + h][ln + 32];
            float mx = fmaxf(x0, x1);
#pragma unroll
            for (int off = 16; off; off >>= 1)
                mx = fmaxf(mx, __shfl_xor_sync(0xffffffffu, mx, off));
            float e0 = (ln < m) ? __expf(x0 - mx) : 0.f;
            float e1 = (ln + 32 < m) ? __expf(x1 - mx) : 0.f;
            float s = e0 + e1;
#pragma unroll
            for (int off = 16; off; off >>= 1)
                s += __shfl_xor_sync(0xffffffffu, s, off);
            float inv = (s > 0.f) ? 1.f / s : 0.f;
            aw[ln * 4 + h] = e0 * inv;
            aw[(ln + 32) * 4 + h] = e1 * inv;
        }
        __syncthreads();

        // u: thread (q = t>>6, i = t&63) handles quarter of j-range, 4 heads
        {
            int q = t >> 6, i = t & 63;
            int ihi = i >> 2, ilo = i & 3;
            int j0 = (m * q) >> 2, j1 = (m * (q + 1)) >> 2;
            u64 u01 = pack2(0.f, 0.f), u23 = u01;
            const ulonglong2* ad = (const ulonglong2*)aw;  // ad[j] = {h01, h23}
            for (int j = j0; j < j1; j++) {
                ulonglong2 a = ad[j];
                float v = ggS[j * 64 + ((ihi ^ (j & 15)) << 2) + ilo];
                u64 vb = pack2(v, v);
                ffma2(u01, vb, a.x);
                ffma2(u23, vb, a.y);
            }
            float2 f01 = unpack2(u01), f23 = unpack2(u23);
            partT[q * 4 + 0][i] = f01.x;
            partT[q * 4 + 1][i] = f01.y;
            partT[q * 4 + 2][i] = f23.x;
            partT[q * 4 + 3][i] = f23.y;
        }
        __syncthreads();

        {   // combine quarters into uT: t = h*64+i
            int h = t >> 6, i = t & 63;
            uT[t * 4 + l] =
                partT[h][i] + partT[4 + h][i] + partT[8 + h][i] + partT[12 + h][i];
        }
        __syncthreads();  // ggS + partT free for next loc
    }

    // --- out phase, batched over 4 locs, f32x2 ---
    {   // thread (h = t>>6, o = t&63)
        int h = t >> 6, o = t & 63;
        const float* Mp = d_M + h * 4096 + o;
        const ulonglong2* ud = (const ulonglong2*)uT + h * 64;  // ud[i] = {l01, l23}
        u64 a01 = pack2(0.f, 0.f), a23 = a01;
#pragma unroll 8
        for (int i = 0; i < 64; i++) {
            float mv = Mp[i * 64];
            u64 mb = pack2(mv, mv);
            ulonglong2 uv = ud[i];
            ffma2(a01, uv.x, mb);
            ffma2(a23, uv.y, mb);
        }
        float2 f01 = unpack2(a01), f23 = unpack2(a23);
        pout[h][o * 4 + 0] = f01.x;
        pout[h][o * 4 + 1] = f01.y;
        pout[h][o * 4 + 2] = f23.x;
        pout[h][o * 4 + 3] = f23.y;
    }
    __syncthreads();

    // final: t<256 -> (l = t>>6, o = t&63); sum heads + bias
    {
        int l = t >> 6, o = t & 63;
        float v = bh[o] + pout[0][o * 4 + l] + pout[1][o * 4 + l] +
                  pout[2][o * 4 + l] + pout[3][o * 4 + l];
        out[(size_t)(g * 4 + l) * 64 + o] = v;
    }
}

// ---------------------------------------------------------------------------
extern "C" void kernel_launch(void* const* d_in, const int* in_sizes, int n_in,
                              void* d_out, int out_size)
{
    const float* g1 = (const float*)d_in[0];
    const float* gg1 = (const float*)d_in[1];
    const int* msk = (const int*)d_in[2];
    const float* Wq = (const float*)d_in[3];
    const float* Wkv = (const float*)d_in[4];
    const float* Wh = (const float*)d_in[5];
    const float* bh = (const float*)d_in[6];
    float* out = (float*)d_out;

    la_precompute<<<dim3(4, 2), 256>>>(Wq, Wkv, Wh);
    la_fused<<<2048, 256>>>(g1, gg1, msk, bh, out);
}